// round 16
// baseline (speedup 1.0000x reference)
#include <cuda_runtime.h>
#include <cuda_bf16.h>
#include <math.h>
#include <stdint.h>

#define BB 4
#define TT 2048
#define HD 128          // head dim
#define NH 8
#define DM (HD*NH)      // 1024
#define MTOT (BB*TT)    // 8192

// Scratch (no cudaMalloc allowed). Q/K/V in bf16 (b,h,t,d); AO fp32.
__device__ uint4 g_Qb[(size_t)BB*NH*TT*HD/8];
__device__ uint4 g_Kb[(size_t)BB*NH*TT*HD/8];
__device__ uint4 g_Vb[(size_t)BB*NH*TT*HD/8];
__device__ float g_AO[(size_t)MTOT*DM];
__device__ uint4 g_xb[(size_t)MTOT*HD/8];        // x in bf16
__device__ uint4 g_Wb[(size_t)3*DM*HD/8];        // Wq|Wk|Wv in bf16 (3072x128)

// ===========================================================================
// PTX helpers
// ===========================================================================
__device__ __forceinline__ uint32_t f2bf2(float lo, float hi) {
    uint32_t r;
    asm("cvt.rn.satfinite.bf16x2.f32 %0, %1, %2;" : "=r"(r) : "f"(hi), "f"(lo));
    return r;
}
__device__ __forceinline__ uint32_t smem_u32(const void* p) {
    uint32_t a;
    asm("{ .reg .u64 t; cvta.to.shared.u64 t, %1; cvt.u32.u64 %0, t; }"
        : "=r"(a) : "l"(p));
    return a;
}
__device__ __forceinline__ void cpasync16(uint32_t dst, const void* src) {
    asm volatile("cp.async.cg.shared.global [%0], [%1], 16;\n"
                 :: "r"(dst), "l"(src) : "memory");
}
#define CP_COMMIT() asm volatile("cp.async.commit_group;\n" ::: "memory")
#define CP_WAIT0()  asm volatile("cp.async.wait_group 0;\n"  ::: "memory")

__device__ __forceinline__ void ldmx4(uint32_t* r, uint32_t addr) {
    asm volatile("ldmatrix.sync.aligned.m8n8.x4.shared.b16 {%0,%1,%2,%3}, [%4];"
                 : "=r"(r[0]), "=r"(r[1]), "=r"(r[2]), "=r"(r[3]) : "r"(addr));
}
__device__ __forceinline__ void ldmx4t(uint32_t* r, uint32_t addr) {
    asm volatile("ldmatrix.sync.aligned.m8n8.x4.trans.shared.b16 {%0,%1,%2,%3}, [%4];"
                 : "=r"(r[0]), "=r"(r[1]), "=r"(r[2]), "=r"(r[3]) : "r"(addr));
}
__device__ __forceinline__ void mma_bf16_k16(float* d,
    uint32_t a0, uint32_t a1, uint32_t a2, uint32_t a3, uint32_t b0, uint32_t b1)
{
    asm volatile(
        "mma.sync.aligned.m16n8k16.row.col.f32.bf16.bf16.f32 "
        "{%0,%1,%2,%3}, {%4,%5,%6,%7}, {%8,%9}, {%0,%1,%2,%3};"
        : "+f"(d[0]), "+f"(d[1]), "+f"(d[2]), "+f"(d[3])
        : "r"(a0), "r"(a1), "r"(a2), "r"(a3), "r"(b0), "r"(b1));
}
__device__ __forceinline__ void mma_tf32_k8(float* d,
    uint32_t a0, uint32_t a1, uint32_t a2, uint32_t a3, uint32_t b0, uint32_t b1)
{
    asm volatile(
        "mma.sync.aligned.m16n8k8.row.col.f32.tf32.tf32.f32 "
        "{%0,%1,%2,%3}, {%4,%5,%6,%7}, {%8,%9}, {%0,%1,%2,%3};"
        : "+f"(d[0]), "+f"(d[1]), "+f"(d[2]), "+f"(d[3])
        : "r"(a0), "r"(a1), "r"(a2), "r"(a3), "r"(b0), "r"(b1));
}

// ===========================================================================
// bf16 convert pre-pass: x (1M elems) + Wq/Wk/Wv (128K each) -> scratch
// ===========================================================================
__global__ __launch_bounds__(256) void cvt_pack(
    const float* __restrict__ x,
    const float* __restrict__ Wq, const float* __restrict__ Wk,
    const float* __restrict__ Wv)
{
    const int i = blockIdx.x * 256 + threadIdx.x;   // one float4 -> uint2
    uint2* xb = (uint2*)g_xb;
    uint2* Wb = (uint2*)g_Wb;
    if (i < MTOT * HD / 4) {
        float4 v = ((const float4*)x)[i];
        xb[i] = make_uint2(f2bf2(v.x, v.y), f2bf2(v.z, v.w));
    }
    if (i < DM * HD / 4) {
        float4 a = ((const float4*)Wq)[i];
        float4 b = ((const float4*)Wk)[i];
        float4 c = ((const float4*)Wv)[i];
        Wb[i]                 = make_uint2(f2bf2(a.x, a.y), f2bf2(a.z, a.w));
        Wb[DM*HD/4 + i]       = make_uint2(f2bf2(b.x, b.y), f2bf2(b.z, b.w));
        Wb[2*(DM*HD/4) + i]   = make_uint2(f2bf2(c.x, c.y), f2bf2(c.z, c.w));
    }
}

// ===========================================================================
// Fused QKV projection, bf16 (known-good from R14/15)
// ===========================================================================
#define PJ_SMEMB (32768 + 16384)

__global__ __launch_bounds__(256, 2) void qkv_bf16(void) {
    extern __shared__ char smc[];
    const uint32_t sb = smem_u32(smc);
    const uint32_t aoff = 0, boff = 32768;

    const int tid = threadIdx.x;
    const int wid = tid >> 5, lane = tid & 31;
    const int grp = lane >> 2, qid = lane & 3;
    const int n0 = blockIdx.x * 64;
    const int mB = blockIdx.y * 128;

    const __nv_bfloat16* xb = (const __nv_bfloat16*)g_xb;
    const __nv_bfloat16* Wb = (const __nv_bfloat16*)g_Wb;

    #pragma unroll
    for (int i = 0; i < 8; i++) {
        int idx = i * 256 + tid;
        int r = idx >> 4, ch = idx & 15;
        cpasync16(sb + aoff + r * 256 + ((ch ^ (r & 7)) << 4),
                  xb + (size_t)(mB + r) * HD + ch * 8);
    }
    #pragma unroll
    for (int i = 0; i < 4; i++) {
        int idx = i * 256 + tid;
        int r = idx >> 4, ch = idx & 15;
        cpasync16(sb + boff + r * 256 + ((ch ^ (r & 7)) << 4),
                  Wb + (size_t)(n0 + r) * HD + ch * 8);
    }
    CP_COMMIT();

    const int t8 = lane >> 3, li = lane & 7;
    const int rowA  = wid * 16 + (t8 & 1) * 8 + li;
    const int kaddA = t8 >> 1;
    const uint32_t baseA = sb + aoff + rowA * 256;
    const int rowKB = (t8 >> 1) * 8 + li;
    const int kaddB = t8 & 1;

    float sacc[8][4];
    #pragma unroll
    for (int nt = 0; nt < 8; nt++)
        #pragma unroll
        for (int j = 0; j < 4; j++) sacc[nt][j] = 0.f;

    CP_WAIT0();
    __syncthreads();

    #pragma unroll
    for (int ks = 0; ks < 8; ks++) {
        uint32_t a[4];
        ldmx4(a, baseA + (((2*ks + kaddA) ^ li) << 4));
        #pragma unroll
        for (int nblk = 0; nblk < 4; nblk++) {
            uint32_t bk[4];
            ldmx4(bk, sb + boff + (nblk * 16 + rowKB) * 256
                       + (((2*ks + kaddB) ^ li) << 4));
            mma_bf16_k16(sacc[2*nblk],   a[0], a[1], a[2], a[3], bk[0], bk[1]);
            mma_bf16_k16(sacc[2*nblk+1], a[0], a[1], a[2], a[3], bk[2], bk[3]);
        }
    }

    const int which = n0 >> 10;             // 0=Q 1=K 2=V
    __nv_bfloat16* dst = (__nv_bfloat16*)(which == 0 ? (void*)g_Qb
                        : which == 1 ? (void*)g_Kb : (void*)g_Vb);
    const int r0 = mB + wid * 16 + grp;
    const int b  = r0 / TT, t0 = r0 % TT;
    #pragma unroll
    for (int nt = 0; nt < 8; nt++) {
        int col = n0 + nt * 8 + 2 * qid;
        int c = col & 1023;
        int hh = c >> 7, d = c & 127;
        size_t base = (((size_t)(b * NH + hh) * TT + t0) << 7) + d;
        *(uint32_t*)(dst + base)            = f2bf2(sacc[nt][0], sacc[nt][1]);
        *(uint32_t*)(dst + base + (8 << 7)) = f2bf2(sacc[nt][2], sacc[nt][3]);
    }
}

// ===========================================================================
// Out-projection v2 (tf32, raw f32 bits): C[8192,128] = AO @ Wu^T + bias.
// BM=64, BN=64, BK=64 -> grid 256 CTAs, 2/SM. Double-buffered cp.async.
// 8 warps: 4 M-blocks x 2 N-halves; each warp m16 x n32. Pitch 68 words.
// ===========================================================================
#define OP_PITCH 68                       // words; row = 272 B (16B-aligned)
#define OP_TILEB (64 * OP_PITCH * 4)      // 17408 B per tile buffer
#define OP_SMEMB (4 * OP_TILEB)           // A0 A1 B0 B1 = 69632 B
#define OP_NPH   (DM / 64)                // 16 K-phases

__global__ __launch_bounds__(256, 2) void out_proj(
    const float* __restrict__ A, const float* __restrict__ W,
    float* __restrict__ C, const float* __restrict__ bias)
{
    extern __shared__ char smc[];
    const uint32_t sb = smem_u32(smc);
    const uint32_t A0 = sb, A1 = sb + OP_TILEB;
    const uint32_t B0 = sb + 2*OP_TILEB, B1 = sb + 3*OP_TILEB;

    const int tid = threadIdx.x;
    const int lane = tid & 31;
    const int grp = lane >> 2, qid = lane & 3;
    const int mw = (tid >> 5) & 3;        // M block
    const int nw = tid >> 7;              // N half
    const int m0 = mw * 16;
    const int nb0 = nw * 32;
    const int mB = blockIdx.y * 64;
    const int n0 = blockIdx.x * 64;

    // staging: 4 chunks of 16B per tile per thread (64 rows x 16 chunks)
    const int str = tid >> 2;             // 0..63 (row)
    const int stc = (tid & 3) * 4;        // chunk base 0,4,8,12

    // prologue: phase 0
    #pragma unroll
    for (int j = 0; j < 4; j++) {
        cpasync16(A0 + str * 272 + (stc + j) * 16,
                  A + (size_t)(mB + str) * DM + (stc + j) * 4);
        cpasync16(B0 + str * 272 + (stc + j) * 16,
                  W + (size_t)(n0 + str) * DM + (stc + j) * 4);
    }
    CP_COMMIT();

    float acc[4][4] = {};

    for (int ph = 0; ph < OP_NPH; ph++) {
        CP_WAIT0();
        __syncthreads();

        const uint32_t Ab = (ph & 1) ? A1 : A0;
        const uint32_t Bb = (ph & 1) ? B1 : B0;

        if (ph + 1 < OP_NPH) {
            const uint32_t An = (ph & 1) ? A0 : A1;
            const uint32_t Bn = (ph & 1) ? B0 : B1;
            const int k1 = (ph + 1) * 64;
            #pragma unroll
            for (int j = 0; j < 4; j++) {
                cpasync16(An + str * 272 + (stc + j) * 16,
                          A + (size_t)(mB + str) * DM + k1 + (stc + j) * 4);
                cpasync16(Bn + str * 272 + (stc + j) * 16,
                          W + (size_t)(n0 + str) * DM + k1 + (stc + j) * 4);
            }
            CP_COMMIT();
        }

        const uint32_t* As = (const uint32_t*)(size_t)0;  // not used; addr math below
        (void)As;
        #pragma unroll
        for (int ks = 0; ks < 8; ks++) {
            int kb = ks * 8;
            uint32_t a0, a1, a2, a3;
            asm volatile("ld.shared.b32 %0, [%1];" : "=r"(a0)
                : "r"(Ab + ((m0 + grp)     * 68 + kb + qid) * 4));
            asm volatile("ld.shared.b32 %0, [%1];" : "=r"(a1)
                : "r"(Ab + ((m0 + grp + 8) * 68 + kb + qid) * 4));
            asm volatile("ld.shared.b32 %0, [%1];" : "=r"(a2)
                : "r"(Ab + ((m0 + grp)     * 68 + kb + qid + 4) * 4));
            asm volatile("ld.shared.b32 %0, [%1];" : "=r"(a3)
                : "r"(Ab + ((m0 + grp + 8) * 68 + kb + qid + 4) * 4));
            #pragma unroll
            for (int nt = 0; nt < 4; nt++) {
                uint32_t b0, b1;
                asm volatile("ld.shared.b32 %0, [%1];" : "=r"(b0)
                    : "r"(Bb + ((nb0 + nt*8 + grp) * 68 + kb + qid) * 4));
                asm volatile("ld.shared.b32 %0, [%1];" : "=r"(b1)
                    : "r"(Bb + ((nb0 + nt*8 + grp) * 68 + kb + qid + 4) * 4));
                mma_tf32_k8(acc[nt], a0, a1, a2, a3, b0, b1);
            }
        }
    }

    const int r0 = mB + m0 + grp;
    const int r1 = r0 + 8;
    #pragma unroll
    for (int nt = 0; nt < 4; nt++) {
        int c = n0 + nb0 + nt * 8 + 2 * qid;
        float b0 = bias[c], b1 = bias[c + 1];
        *(float2*)&C[(size_t)r0 * HD + c] =
            make_float2(acc[nt][0] + b0, acc[nt][1] + b1);
        *(float2*)&C[(size_t)r1 * HD + c] =
            make_float2(acc[nt][2] + b0, acc[nt][3] + b1);
    }
}

// ===========================================================================
// Flash attention v6 (unchanged from R13): FA2-style register-P.
// ===========================================================================
#define BM 128
#define BN 64
#define NIT (TT/BN)
#define QOFF  0
#define K0OFF 32768
#define V0OFF 49152
#define K1OFF 65536
#define V1OFF 81920
#define SMEMB 98304

__global__ __launch_bounds__(256, 2) void flash_mma6(
    const __nv_bfloat16* __restrict__ gQ, const __nv_bfloat16* __restrict__ gK,
    const __nv_bfloat16* __restrict__ gV, float* __restrict__ gAO)
{
    const int qt = blockIdx.x, h = blockIdx.y, b = blockIdx.z;
    const int tid  = threadIdx.x;
    const int wid  = tid >> 5;
    const int lane = tid & 31;
    const int grp  = lane >> 2;
    const int qid  = lane & 3;

    extern __shared__ char smc[];
    const uint32_t sb = smem_u32(smc);

    const size_t base = ((size_t)(b*NH + h) * TT) * HD;
    const __nv_bfloat16* Qg = gQ + base + (size_t)qt * BM * HD;
    const __nv_bfloat16* Kh = gK + base;
    const __nv_bfloat16* Vh = gV + base;

    #pragma unroll
    for (int i = 0; i < 8; i++) {
        int idx = i * 256 + tid;
        int r = idx >> 4, ch = idx & 15;
        cpasync16(sb + QOFF + r * 256 + ((ch ^ (r & 7)) << 4),
                  Qg + (size_t)r * HD + ch * 8);
    }
    #pragma unroll
    for (int i = 0; i < 4; i++) {
        int idx = i * 256 + tid;
        int r = idx >> 4, ch = idx & 15;
        int sw = r * 256 + ((ch ^ (r & 7)) << 4);
        cpasync16(sb + K0OFF + sw, Kh + (size_t)r * HD + ch * 8);
        cpasync16(sb + V0OFF + sw, Vh + (size_t)r * HD + ch * 8);
    }
    CP_COMMIT();

    const int t8 = lane >> 3, li = lane & 7;
    const int rowA  = wid * 16 + (t8 & 1) * 8 + li;
    const int kaddA = t8 >> 1;
    const uint32_t baseQA = sb + QOFF + rowA * 256;
    const int rowKB = (t8 >> 1) * 8 + li;
    const int kaddB = t8 & 1;
    const int vrow  = (t8 & 1) * 8 + li;
    const int vcadd = t8 >> 1;

    float oacc[16][4];
    #pragma unroll
    for (int nt = 0; nt < 16; nt++)
        #pragma unroll
        for (int j = 0; j < 4; j++) oacc[nt][j] = 0.f;
    float l0 = 0.f, l1 = 0.f;
    const float scale = 0.08838834764831845f;

    for (int it = 0; it < NIT; it++) {
        CP_WAIT0();
        __syncthreads();

        const uint32_t kbuf = (it & 1) ? sb + K1OFF : sb + K0OFF;
        const uint32_t vbuf = (it & 1) ? sb + V1OFF : sb + V0OFF;

        if (it + 1 < NIT) {
            const uint32_t kn = (it & 1) ? sb + K0OFF : sb + K1OFF;
            const uint32_t vn = (it & 1) ? sb + V0OFF : sb + V1OFF;
            const __nv_bfloat16* Kg = Kh + (size_t)(it + 1) * BN * HD;
            const __nv_bfloat16* Vg = Vh + (size_t)(it + 1) * BN * HD;
            #pragma unroll
            for (int i = 0; i < 4; i++) {
                int idx = i * 256 + tid;
                int r = idx >> 4, ch = idx & 15;
                int sw = r * 256 + ((ch ^ (r & 7)) << 4);
                cpasync16(kn + sw, Kg + (size_t)r * HD + ch * 8);
                cpasync16(vn + sw, Vg + (size_t)r * HD + ch * 8);
            }
            CP_COMMIT();
        }

        float sacc[8][4];
        #pragma unroll
        for (int nt = 0; nt < 8; nt++)
            #pragma unroll
            for (int j = 0; j < 4; j++) sacc[nt][j] = 0.f;

        #pragma unroll
        for (int ks = 0; ks < 8; ks++) {
            uint32_t a[4];
            ldmx4(a, baseQA + (((2*ks + kaddA) ^ li) << 4));
            #pragma unroll
            for (int nblk = 0; nblk < 4; nblk++) {
                uint32_t bk[4];
                ldmx4(bk, kbuf + (nblk * 16 + rowKB) * 256
                           + (((2*ks + kaddB) ^ li) << 4));
                mma_bf16_k16(sacc[2*nblk],   a[0], a[1], a[2], a[3], bk[0], bk[1]);
                mma_bf16_k16(sacc[2*nblk+1], a[0], a[1], a[2], a[3], bk[2], bk[3]);
            }
        }

        uint32_t pf[4][4];
        #pragma unroll
        for (int nt = 0; nt < 8; nt++) {
            float p0 = __expf(sacc[nt][0] * scale);
            float p1 = __expf(sacc[nt][1] * scale);
            float p2 = __expf(sacc[nt][2] * scale);
            float p3 = __expf(sacc[nt][3] * scale);
            l0 += p0 + p1;
            l1 += p2 + p3;
            pf[nt >> 1][(nt & 1) * 2 + 0] = f2bf2(p0, p1);
            pf[nt >> 1][(nt & 1) * 2 + 1] = f2bf2(p2, p3);
        }

        #pragma unroll
        for (int ks = 0; ks < 4; ks++) {
            int kr = ks * 16 + vrow;
            uint32_t vbase = vbuf + kr * 256;
            #pragma unroll
            for (int dblk = 0; dblk < 8; dblk++) {
                uint32_t v[4];
                int ch = dblk * 2 + vcadd;
                ldmx4t(v, vbase + ((ch ^ li) << 4));
                mma_bf16_k16(oacc[dblk*2],   pf[ks][0], pf[ks][1], pf[ks][2],
                             pf[ks][3], v[0], v[1]);
                mma_bf16_k16(oacc[dblk*2+1], pf[ks][0], pf[ks][1], pf[ks][2],
                             pf[ks][3], v[2], v[3]);
            }
        }
    }

    l0 += __shfl_xor_sync(0xffffffffu, l0, 1);
    l0 += __shfl_xor_sync(0xffffffffu, l0, 2);
    l1 += __shfl_xor_sync(0xffffffffu, l1, 1);
    l1 += __shfl_xor_sync(0xffffffffu, l1, 2);
    const float inv0 = 1.f / l0;
    const float inv1 = 1.f / l1;

    const int t0 = qt * BM + wid * 16 + grp;
    float* o0 = gAO + ((size_t)(b * TT + t0)) * DM + h * HD;
    float* o1 = o0 + 8 * (size_t)DM;
    #pragma unroll
    for (int nt = 0; nt < 16; nt++) {
        int c = nt * 8 + 2 * qid;
        *(float2*)(o0 + c) = make_float2(oacc[nt][0] * inv0, oacc[nt][1] * inv0);
        *(float2*)(o1 + c) = make_float2(oacc[nt][2] * inv1, oacc[nt][3] * inv1);
    }
}

// ===========================================================================
extern "C" void kernel_launch(void* const* d_in, const int* in_sizes, int n_in,
                              void* d_out, int out_size)
{
    const float* x  = (const float*)d_in[0];
    const float* Wq = (const float*)d_in[1];
    const float* Wk = (const float*)d_in[2];
    const float* Wv = (const float*)d_in[3];
    const float* Wu = (const float*)d_in[4];
    const float* bu = (const float*)d_in[5];
    float* out = (float*)d_out;

    void *Qb, *Kb, *Vb;
    float* AOp;
    cudaGetSymbolAddress(&Qb, g_Qb);
    cudaGetSymbolAddress(&Kb, g_Kb);
    cudaGetSymbolAddress(&Vb, g_Vb);
    cudaGetSymbolAddress((void**)&AOp, g_AO);

    cudaFuncSetAttribute(qkv_bf16, cudaFuncAttributeMaxDynamicSharedMemorySize,
                         PJ_SMEMB);
    cudaFuncSetAttribute(out_proj, cudaFuncAttributeMaxDynamicSharedMemorySize,
                         OP_SMEMB);
    cudaFuncSetAttribute(flash_mma6, cudaFuncAttributeMaxDynamicSharedMemorySize,
                         SMEMB);

    // 1) convert x + W to bf16 scratch
    cvt_pack<<<(MTOT*HD/4 + 255)/256, 256>>>(x, Wq, Wk, Wv);

    // 2) fused QKV projection (bf16, ldmatrix), scatter to (b,h,t,d)
    qkv_bf16<<<dim3(3*DM/64, MTOT/128), 256, PJ_SMEMB>>>();

    // 3) flash attention (register-P FA2, double-buffered cp.async)
    flash_mma6<<<dim3(TT/BM, NH, BB), 256, SMEMB>>>(
        (const __nv_bfloat16*)Qb, (const __nv_bfloat16*)Kb,
        (const __nv_bfloat16*)Vb, AOp);

    // 4) output projection v2 (tf32 raw-bits, double-buffered cp.async)
    out_proj<<<dim3(HD/64, MTOT/64), 256, OP_SMEMB>>>(AOp, Wu, out, bu);
}

// round 17
// speedup vs baseline: 1.1020x; 1.1020x over previous
#include <cuda_runtime.h>
#include <cuda_bf16.h>
#include <cuda_fp16.h>
#include <math.h>
#include <stdint.h>

#define BB 4
#define TT 2048
#define HD 128          // head dim
#define NH 8
#define DM (HD*NH)      // 1024
#define MTOT (BB*TT)    // 8192

// Scratch (no cudaMalloc allowed).
__device__ uint4 g_Qb[(size_t)BB*NH*TT*HD/8];    // bf16 (b,h,t,d)
__device__ uint4 g_Kb[(size_t)BB*NH*TT*HD/8];
__device__ uint4 g_Vb[(size_t)BB*NH*TT*HD/8];
__device__ uint4 g_AOh[(size_t)MTOT*DM/8];       // AO fp16 (b,t, h*128+d)
__device__ uint4 g_xb[(size_t)MTOT*HD/8];        // x bf16
__device__ uint4 g_Wb[(size_t)3*DM*HD/8];        // Wq|Wk|Wv bf16 (3072x128)
__device__ uint4 g_Wuh[(size_t)HD*DM/8];         // Wu fp16 (128x1024)

// ===========================================================================
// PTX helpers
// ===========================================================================
__device__ __forceinline__ uint32_t f2bf2(float lo, float hi) {
    uint32_t r;
    asm("cvt.rn.satfinite.bf16x2.f32 %0, %1, %2;" : "=r"(r) : "f"(hi), "f"(lo));
    return r;
}
__device__ __forceinline__ uint32_t f2h2(float lo, float hi) {
    uint32_t r;
    asm("cvt.rn.f16x2.f32 %0, %1, %2;" : "=r"(r) : "f"(hi), "f"(lo));
    return r;
}
__device__ __forceinline__ uint32_t smem_u32(const void* p) {
    uint32_t a;
    asm("{ .reg .u64 t; cvta.to.shared.u64 t, %1; cvt.u32.u64 %0, t; }"
        : "=r"(a) : "l"(p));
    return a;
}
__device__ __forceinline__ void cpasync16(uint32_t dst, const void* src) {
    asm volatile("cp.async.cg.shared.global [%0], [%1], 16;\n"
                 :: "r"(dst), "l"(src) : "memory");
}
#define CP_COMMIT() asm volatile("cp.async.commit_group;\n" ::: "memory")
#define CP_WAIT0()  asm volatile("cp.async.wait_group 0;\n"  ::: "memory")
#define CP_WAIT1()  asm volatile("cp.async.wait_group 1;\n"  ::: "memory")

__device__ __forceinline__ void ldmx4(uint32_t* r, uint32_t addr) {
    asm volatile("ldmatrix.sync.aligned.m8n8.x4.shared.b16 {%0,%1,%2,%3}, [%4];"
                 : "=r"(r[0]), "=r"(r[1]), "=r"(r[2]), "=r"(r[3]) : "r"(addr));
}
__device__ __forceinline__ void ldmx4t(uint32_t* r, uint32_t addr) {
    asm volatile("ldmatrix.sync.aligned.m8n8.x4.trans.shared.b16 {%0,%1,%2,%3}, [%4];"
                 : "=r"(r[0]), "=r"(r[1]), "=r"(r[2]), "=r"(r[3]) : "r"(addr));
}
__device__ __forceinline__ void mma_bf16_k16(float* d,
    uint32_t a0, uint32_t a1, uint32_t a2, uint32_t a3, uint32_t b0, uint32_t b1)
{
    asm volatile(
        "mma.sync.aligned.m16n8k16.row.col.f32.bf16.bf16.f32 "
        "{%0,%1,%2,%3}, {%4,%5,%6,%7}, {%8,%9}, {%0,%1,%2,%3};"
        : "+f"(d[0]), "+f"(d[1]), "+f"(d[2]), "+f"(d[3])
        : "r"(a0), "r"(a1), "r"(a2), "r"(a3), "r"(b0), "r"(b1));
}
__device__ __forceinline__ void mma_f16_k16(float* d,
    uint32_t a0, uint32_t a1, uint32_t a2, uint32_t a3, uint32_t b0, uint32_t b1)
{
    asm volatile(
        "mma.sync.aligned.m16n8k16.row.col.f32.f16.f16.f32 "
        "{%0,%1,%2,%3}, {%4,%5,%6,%7}, {%8,%9}, {%0,%1,%2,%3};"
        : "+f"(d[0]), "+f"(d[1]), "+f"(d[2]), "+f"(d[3])
        : "r"(a0), "r"(a1), "r"(a2), "r"(a3), "r"(b0), "r"(b1));
}

// ===========================================================================
// convert pre-pass: x, Wq/Wk/Wv -> bf16 ; Wu -> fp16
// ===========================================================================
__global__ __launch_bounds__(256) void cvt_pack(
    const float* __restrict__ x,
    const float* __restrict__ Wq, const float* __restrict__ Wk,
    const float* __restrict__ Wv, const float* __restrict__ Wu)
{
    const int i = blockIdx.x * 256 + threadIdx.x;   // one float4 -> uint2
    uint2* xb = (uint2*)g_xb;
    uint2* Wb = (uint2*)g_Wb;
    uint2* Wuh = (uint2*)g_Wuh;
    if (i < MTOT * HD / 4) {
        float4 v = ((const float4*)x)[i];
        xb[i] = make_uint2(f2bf2(v.x, v.y), f2bf2(v.z, v.w));
    }
    if (i < DM * HD / 4) {
        float4 a = ((const float4*)Wq)[i];
        float4 b = ((const float4*)Wk)[i];
        float4 c = ((const float4*)Wv)[i];
        Wb[i]                 = make_uint2(f2bf2(a.x, a.y), f2bf2(a.z, a.w));
        Wb[DM*HD/4 + i]       = make_uint2(f2bf2(b.x, b.y), f2bf2(b.z, b.w));
        Wb[2*(DM*HD/4) + i]   = make_uint2(f2bf2(c.x, c.y), f2bf2(c.z, c.w));
    }
    if (i < HD * DM / 4) {
        float4 u = ((const float4*)Wu)[i];
        Wuh[i] = make_uint2(f2h2(u.x, u.y), f2h2(u.z, u.w));
    }
}

// ===========================================================================
// Fused QKV projection, bf16 (known-good from R14/15)
// ===========================================================================
#define PJ_SMEMB (32768 + 16384)

__global__ __launch_bounds__(256, 2) void qkv_bf16(void) {
    extern __shared__ char smc[];
    const uint32_t sb = smem_u32(smc);
    const uint32_t aoff = 0, boff = 32768;

    const int tid = threadIdx.x;
    const int wid = tid >> 5, lane = tid & 31;
    const int grp = lane >> 2, qid = lane & 3;
    const int n0 = blockIdx.x * 64;
    const int mB = blockIdx.y * 128;

    const __nv_bfloat16* xb = (const __nv_bfloat16*)g_xb;
    const __nv_bfloat16* Wb = (const __nv_bfloat16*)g_Wb;

    #pragma unroll
    for (int i = 0; i < 8; i++) {
        int idx = i * 256 + tid;
        int r = idx >> 4, ch = idx & 15;
        cpasync16(sb + aoff + r * 256 + ((ch ^ (r & 7)) << 4),
                  xb + (size_t)(mB + r) * HD + ch * 8);
    }
    #pragma unroll
    for (int i = 0; i < 4; i++) {
        int idx = i * 256 + tid;
        int r = idx >> 4, ch = idx & 15;
        cpasync16(sb + boff + r * 256 + ((ch ^ (r & 7)) << 4),
                  Wb + (size_t)(n0 + r) * HD + ch * 8);
    }
    CP_COMMIT();

    const int t8 = lane >> 3, li = lane & 7;
    const int rowA  = wid * 16 + (t8 & 1) * 8 + li;
    const int kaddA = t8 >> 1;
    const uint32_t baseA = sb + aoff + rowA * 256;
    const int rowKB = (t8 >> 1) * 8 + li;
    const int kaddB = t8 & 1;

    float sacc[8][4];
    #pragma unroll
    for (int nt = 0; nt < 8; nt++)
        #pragma unroll
        for (int j = 0; j < 4; j++) sacc[nt][j] = 0.f;

    CP_WAIT0();
    __syncthreads();

    #pragma unroll
    for (int ks = 0; ks < 8; ks++) {
        uint32_t a[4];
        ldmx4(a, baseA + (((2*ks + kaddA) ^ li) << 4));
        #pragma unroll
        for (int nblk = 0; nblk < 4; nblk++) {
            uint32_t bk[4];
            ldmx4(bk, sb + boff + (nblk * 16 + rowKB) * 256
                       + (((2*ks + kaddB) ^ li) << 4));
            mma_bf16_k16(sacc[2*nblk],   a[0], a[1], a[2], a[3], bk[0], bk[1]);
            mma_bf16_k16(sacc[2*nblk+1], a[0], a[1], a[2], a[3], bk[2], bk[3]);
        }
    }

    const int which = n0 >> 10;             // 0=Q 1=K 2=V
    __nv_bfloat16* dst = (__nv_bfloat16*)(which == 0 ? (void*)g_Qb
                        : which == 1 ? (void*)g_Kb : (void*)g_Vb);
    const int r0 = mB + wid * 16 + grp;
    const int b  = r0 / TT, t0 = r0 % TT;
    #pragma unroll
    for (int nt = 0; nt < 8; nt++) {
        int col = n0 + nt * 8 + 2 * qid;
        int c = col & 1023;
        int hh = c >> 7, d = c & 127;
        size_t base = (((size_t)(b * NH + hh) * TT + t0) << 7) + d;
        *(uint32_t*)(dst + base)            = f2bf2(sacc[nt][0], sacc[nt][1]);
        *(uint32_t*)(dst + base + (8 << 7)) = f2bf2(sacc[nt][2], sacc[nt][3]);
    }
}

// ===========================================================================
// Out-projection v3 (fp16, ldmatrix, 3-stage cp.async pipeline):
// C[8192,128] = AOh @ Wuh^T + bias. BM=64, BN=64, BK=128 (8 phases).
// grid (2,128)=256 CTAs, 2/SM. 8 warps: 4 M-blocks x 2 N-halves (m16 x n32).
// ===========================================================================
#define OPH_STG   32768                 // A 64x256B + B 64x256B
#define OPH_SMEMB (3 * OPH_STG)         // 98304
#define OPH_NPH   (DM / 128)            // 8

__global__ __launch_bounds__(256, 2) void out_proj_h(
    float* __restrict__ C, const float* __restrict__ bias)
{
    extern __shared__ char smc[];
    const uint32_t sb = smem_u32(smc);

    const int tid = threadIdx.x;
    const int lane = tid & 31;
    const int grp = lane >> 2, qid = lane & 3;
    const int mw = (tid >> 5) & 3;
    const int nw = tid >> 7;
    const int m0 = mw * 16;
    const int nb0 = nw * 32;
    const int n0 = blockIdx.x * 64;
    const int mB = blockIdx.y * 64;

    const __half* Ah = (const __half*)g_AOh;
    const __half* Wh = (const __half*)g_Wuh;

    // staging coords: 4 chunks/thread per 64x(128 fp16) tile
    const int str = tid >> 2;             // row 0..63
    const int stc4 = (tid & 3) * 4;       // chunk base

    // stage phase ph into buffer (ph % 3)
    auto stage = [&](int ph) {
        const uint32_t bbase = sb + (ph % 3) * OPH_STG;
        const int kofs = ph * 128;
        #pragma unroll
        for (int j = 0; j < 4; j++) {
            int ch = stc4 + j;
            int sw = str * 256 + ((ch ^ (str & 7)) << 4);
            cpasync16(bbase + sw,         Ah + (size_t)(mB + str) * DM + kofs + ch * 8);
            cpasync16(bbase + 16384 + sw, Wh + (size_t)(n0 + str) * DM + kofs + ch * 8);
        }
        CP_COMMIT();
    };

    stage(0);
    stage(1);

    const int t8 = lane >> 3, li = lane & 7;
    const int rowA  = m0 + (t8 & 1) * 8 + li;
    const int kaddA = t8 >> 1;
    const int rowKB = (t8 >> 1) * 8 + li;
    const int kaddB = t8 & 1;

    float acc[4][4] = {};

    for (int ph = 0; ph < OPH_NPH; ph++) {
        if (ph + 1 < OPH_NPH) CP_WAIT1();
        else                  CP_WAIT0();
        __syncthreads();

        if (ph + 2 < OPH_NPH) stage(ph + 2);

        const uint32_t Ab = sb + (ph % 3) * OPH_STG;
        const uint32_t Bb = Ab + 16384;
        const uint32_t baseA = Ab + rowA * 256;

        #pragma unroll
        for (int ks = 0; ks < 8; ks++) {
            uint32_t a[4];
            ldmx4(a, baseA + (((2*ks + kaddA) ^ li) << 4));
            #pragma unroll
            for (int nblk = 0; nblk < 2; nblk++) {
                uint32_t bk[4];
                ldmx4(bk, Bb + (nb0 + nblk * 16 + rowKB) * 256
                           + (((2*ks + kaddB) ^ li) << 4));
                mma_f16_k16(acc[2*nblk],   a[0], a[1], a[2], a[3], bk[0], bk[1]);
                mma_f16_k16(acc[2*nblk+1], a[0], a[1], a[2], a[3], bk[2], bk[3]);
            }
        }
    }

    const int r0 = mB + m0 + grp;
    const int r1 = r0 + 8;
    #pragma unroll
    for (int nt = 0; nt < 4; nt++) {
        int c = n0 + nb0 + nt * 8 + 2 * qid;
        float b0 = bias[c], b1 = bias[c + 1];
        *(float2*)&C[(size_t)r0 * HD + c] =
            make_float2(acc[nt][0] + b0, acc[nt][1] + b1);
        *(float2*)&C[(size_t)r1 * HD + c] =
            make_float2(acc[nt][2] + b0, acc[nt][3] + b1);
    }
}

// ===========================================================================
// Flash attention v6 (R13 core; epilogue now writes fp16 AO)
// ===========================================================================
#define BM 128
#define BN 64
#define NIT (TT/BN)
#define QOFF  0
#define K0OFF 32768
#define V0OFF 49152
#define K1OFF 65536
#define V1OFF 81920
#define SMEMB 98304

__global__ __launch_bounds__(256, 2) void flash_mma6(
    const __nv_bfloat16* __restrict__ gQ, const __nv_bfloat16* __restrict__ gK,
    const __nv_bfloat16* __restrict__ gV, __half* __restrict__ gAO)
{
    const int qt = blockIdx.x, h = blockIdx.y, b = blockIdx.z;
    const int tid  = threadIdx.x;
    const int wid  = tid >> 5;
    const int lane = tid & 31;
    const int grp  = lane >> 2;
    const int qid  = lane & 3;

    extern __shared__ char smc[];
    const uint32_t sb = smem_u32(smc);

    const size_t base = ((size_t)(b*NH + h) * TT) * HD;
    const __nv_bfloat16* Qg = gQ + base + (size_t)qt * BM * HD;
    const __nv_bfloat16* Kh = gK + base;
    const __nv_bfloat16* Vh = gV + base;

    #pragma unroll
    for (int i = 0; i < 8; i++) {
        int idx = i * 256 + tid;
        int r = idx >> 4, ch = idx & 15;
        cpasync16(sb + QOFF + r * 256 + ((ch ^ (r & 7)) << 4),
                  Qg + (size_t)r * HD + ch * 8);
    }
    #pragma unroll
    for (int i = 0; i < 4; i++) {
        int idx = i * 256 + tid;
        int r = idx >> 4, ch = idx & 15;
        int sw = r * 256 + ((ch ^ (r & 7)) << 4);
        cpasync16(sb + K0OFF + sw, Kh + (size_t)r * HD + ch * 8);
        cpasync16(sb + V0OFF + sw, Vh + (size_t)r * HD + ch * 8);
    }
    CP_COMMIT();

    const int t8 = lane >> 3, li = lane & 7;
    const int rowA  = wid * 16 + (t8 & 1) * 8 + li;
    const int kaddA = t8 >> 1;
    const uint32_t baseQA = sb + QOFF + rowA * 256;
    const int rowKB = (t8 >> 1) * 8 + li;
    const int kaddB = t8 & 1;
    const int vrow  = (t8 & 1) * 8 + li;
    const int vcadd = t8 >> 1;

    float oacc[16][4];
    #pragma unroll
    for (int nt = 0; nt < 16; nt++)
        #pragma unroll
        for (int j = 0; j < 4; j++) oacc[nt][j] = 0.f;
    float l0 = 0.f, l1 = 0.f;
    const float scale = 0.08838834764831845f;

    for (int it = 0; it < NIT; it++) {
        CP_WAIT0();
        __syncthreads();

        const uint32_t kbuf = (it & 1) ? sb + K1OFF : sb + K0OFF;
        const uint32_t vbuf = (it & 1) ? sb + V1OFF : sb + V0OFF;

        if (it + 1 < NIT) {
            const uint32_t kn = (it & 1) ? sb + K0OFF : sb + K1OFF;
            const uint32_t vn = (it & 1) ? sb + V0OFF : sb + V1OFF;
            const __nv_bfloat16* Kg = Kh + (size_t)(it + 1) * BN * HD;
            const __nv_bfloat16* Vg = Vh + (size_t)(it + 1) * BN * HD;
            #pragma unroll
            for (int i = 0; i < 4; i++) {
                int idx = i * 256 + tid;
                int r = idx >> 4, ch = idx & 15;
                int sw = r * 256 + ((ch ^ (r & 7)) << 4);
                cpasync16(kn + sw, Kg + (size_t)r * HD + ch * 8);
                cpasync16(vn + sw, Vg + (size_t)r * HD + ch * 8);
            }
            CP_COMMIT();
        }

        float sacc[8][4];
        #pragma unroll
        for (int nt = 0; nt < 8; nt++)
            #pragma unroll
            for (int j = 0; j < 4; j++) sacc[nt][j] = 0.f;

        #pragma unroll
        for (int ks = 0; ks < 8; ks++) {
            uint32_t a[4];
            ldmx4(a, baseQA + (((2*ks + kaddA) ^ li) << 4));
            #pragma unroll
            for (int nblk = 0; nblk < 4; nblk++) {
                uint32_t bk[4];
                ldmx4(bk, kbuf + (nblk * 16 + rowKB) * 256
                           + (((2*ks + kaddB) ^ li) << 4));
                mma_bf16_k16(sacc[2*nblk],   a[0], a[1], a[2], a[3], bk[0], bk[1]);
                mma_bf16_k16(sacc[2*nblk+1], a[0], a[1], a[2], a[3], bk[2], bk[3]);
            }
        }

        uint32_t pf[4][4];
        #pragma unroll
        for (int nt = 0; nt < 8; nt++) {
            float p0 = __expf(sacc[nt][0] * scale);
            float p1 = __expf(sacc[nt][1] * scale);
            float p2 = __expf(sacc[nt][2] * scale);
            float p3 = __expf(sacc[nt][3] * scale);
            l0 += p0 + p1;
            l1 += p2 + p3;
            pf[nt >> 1][(nt & 1) * 2 + 0] = f2bf2(p0, p1);
            pf[nt >> 1][(nt & 1) * 2 + 1] = f2bf2(p2, p3);
        }

        #pragma unroll
        for (int ks = 0; ks < 4; ks++) {
            int kr = ks * 16 + vrow;
            uint32_t vbase = vbuf + kr * 256;
            #pragma unroll
            for (int dblk = 0; dblk < 8; dblk++) {
                uint32_t v[4];
                int ch = dblk * 2 + vcadd;
                ldmx4t(v, vbase + ((ch ^ li) << 4));
                mma_bf16_k16(oacc[dblk*2],   pf[ks][0], pf[ks][1], pf[ks][2],
                             pf[ks][3], v[0], v[1]);
                mma_bf16_k16(oacc[dblk*2+1], pf[ks][0], pf[ks][1], pf[ks][2],
                             pf[ks][3], v[2], v[3]);
            }
        }
    }

    l0 += __shfl_xor_sync(0xffffffffu, l0, 1);
    l0 += __shfl_xor_sync(0xffffffffu, l0, 2);
    l1 += __shfl_xor_sync(0xffffffffu, l1, 1);
    l1 += __shfl_xor_sync(0xffffffffu, l1, 2);
    const float inv0 = 1.f / l0;
    const float inv1 = 1.f / l1;

    const int t0 = qt * BM + wid * 16 + grp;
    __half* o0 = gAO + ((size_t)(b * TT + t0)) * DM + h * HD;
    __half* o1 = o0 + 8 * (size_t)DM;
    #pragma unroll
    for (int nt = 0; nt < 16; nt++) {
        int c = nt * 8 + 2 * qid;
        *(uint32_t*)(o0 + c) = f2h2(oacc[nt][0] * inv0, oacc[nt][1] * inv0);
        *(uint32_t*)(o1 + c) = f2h2(oacc[nt][2] * inv1, oacc[nt][3] * inv1);
    }
}

// ===========================================================================
extern "C" void kernel_launch(void* const* d_in, const int* in_sizes, int n_in,
                              void* d_out, int out_size)
{
    const float* x  = (const float*)d_in[0];
    const float* Wq = (const float*)d_in[1];
    const float* Wk = (const float*)d_in[2];
    const float* Wv = (const float*)d_in[3];
    const float* Wu = (const float*)d_in[4];
    const float* bu = (const float*)d_in[5];
    float* out = (float*)d_out;

    void *Qb, *Kb, *Vb, *AOh;
    cudaGetSymbolAddress(&Qb, g_Qb);
    cudaGetSymbolAddress(&Kb, g_Kb);
    cudaGetSymbolAddress(&Vb, g_Vb);
    cudaGetSymbolAddress(&AOh, g_AOh);

    cudaFuncSetAttribute(qkv_bf16, cudaFuncAttributeMaxDynamicSharedMemorySize,
                         PJ_SMEMB);
    cudaFuncSetAttribute(out_proj_h, cudaFuncAttributeMaxDynamicSharedMemorySize,
                         OPH_SMEMB);
    cudaFuncSetAttribute(flash_mma6, cudaFuncAttributeMaxDynamicSharedMemorySize,
                         SMEMB);

    // 1) convert x + Wq/Wk/Wv (bf16) + Wu (fp16)
    cvt_pack<<<(MTOT*HD/4 + 255)/256, 256>>>(x, Wq, Wk, Wv, Wu);

    // 2) fused QKV projection (bf16, ldmatrix), scatter to (b,h,t,d)
    qkv_bf16<<<dim3(3*DM/64, MTOT/128), 256, PJ_SMEMB>>>();

    // 3) flash attention (register-P FA2), writes fp16 AO
    flash_mma6<<<dim3(TT/BM, NH, BB), 256, SMEMB>>>(
        (const __nv_bfloat16*)Qb, (const __nv_bfloat16*)Kb,
        (const __nv_bfloat16*)Vb, (__half*)AOh);

    // 4) output projection v3 (fp16, ldmatrix, 3-stage pipeline)
    out_proj_h<<<dim3(HD/64, MTOT/64), 256, OPH_SMEMB>>>(out, bu);
}